// round 16
// baseline (speedup 1.0000x reference)
#include <cuda_runtime.h>
#include <cstdint>

// out[i] = W[inputs[i] - 1];  N = 16384*200 = 3,276,800;  W: 200 floats.
// Probe idx_raw[1]: ==0 -> int64 indices, !=0 -> int32.
//
// Hybrid of the two best designs (R7 direct streaming stores, R14 bulk-DMA
// loads): triple-buffered cp.async.bulk index loads into smem; per-thread
// work = one LDS.128 (2 idx), 2 conflict-free replicated-sW gathers, one
// direct __stcs float2 store. One __syncthreads per chunk. 592 CTAs x 512.

#define N_TOTAL    (16384 * 200)
#define MAX_RANKS  200
#define TPB        512
#define NCTAS      592                      // 148 SMs * 4 CTAs
#define NSTAGES    3
#define EPC        1024                     // elems per chunk (2/thread)
#define NCHUNKS    (N_TOTAL / EPC)          // 3200

__device__ __forceinline__ uint32_t smem_u32(const void* p) {
    uint32_t a;
    asm("{ .reg .u64 t; cvta.to.shared.u64 t, %1; cvt.u32.u64 %0, t; }"
        : "=r"(a) : "l"(p));
    return a;
}
__device__ __forceinline__ void mbar_init(uint32_t m, uint32_t c) {
    asm volatile("mbarrier.init.shared.b64 [%0], %1;" :: "r"(m), "r"(c) : "memory");
}
__device__ __forceinline__ void bulk_load(uint32_t dst, const void* src,
                                          uint32_t bytes, uint32_t mbar) {
    asm volatile("mbarrier.arrive.expect_tx.shared::cta.b64 _, [%0], %1;"
                 :: "r"(mbar), "r"(bytes) : "memory");
    asm volatile("cp.async.bulk.shared::cta.global.mbarrier::complete_tx::bytes "
                 "[%0], [%1], %2, [%3];"
                 :: "r"(dst), "l"(src), "r"(bytes), "r"(mbar) : "memory");
}
__device__ __forceinline__ void mbar_wait(uint32_t m, uint32_t parity) {
    asm volatile(
        "{\n\t.reg .pred P;\n\t"
        "WL_%=:\n\t"
        "mbarrier.try_wait.parity.acquire.cta.shared::cta.b64 P, [%0], %1, 0x989680;\n\t"
        "@!P bra WL_%=;\n\t}"
        :: "r"(m), "r"(parity) : "memory");
}

__global__ __launch_bounds__(TPB)
void bias_gather_kernel(const uint32_t* __restrict__ idx_raw,
                        const float* __restrict__ W,
                        float* __restrict__ out)
{
    __shared__ float sW[MAX_RANKS * 32];                                // 25600 B
    __shared__ __align__(16) unsigned long long ibuf[NSTAGES][EPC];     // 3 x 8192 B
    __shared__ __align__(8)  unsigned long long mbar_s[NSTAGES];

    const int tid  = threadIdx.x;
    const int lane = tid & 31;
    const int wid  = tid >> 5;
    const int bid  = blockIdx.x;

    const uint32_t probe = idx_raw[1];          // 0 => int64 indices
    const bool is64 = (probe == 0u);
    const uint32_t ic_bytes = is64 ? EPC * 8 : EPC * 4;

    uint32_t mb[NSTAGES], ib[NSTAGES];
    #pragma unroll
    for (int s = 0; s < NSTAGES; s++) {
        mb[s] = smem_u32(&mbar_s[s]);
        ib[s] = smem_u32(&ibuf[s][0]);
    }

    if (tid == 0) {
        #pragma unroll
        for (int s = 0; s < NSTAGES; s++) mbar_init(mb[s], 1);
    }
    __syncthreads();

    const char* gsrc = reinterpret_cast<const char*>(idx_raw);

    // Prefill all 3 stages.
    if (tid == 0) {
        #pragma unroll
        for (int s = 0; s < NSTAGES; s++) {
            long long c = bid + (long long)s * NCTAS;
            if (c < NCHUNKS) bulk_load(ib[s], gsrc + c * ic_bytes, ic_bytes, mb[s]);
        }
    }

    // Fill replicated W while the DMAs fly.
    #pragma unroll
    for (int k = wid; k < MAX_RANKS; k += TPB / 32) {
        float v = W[k];                  // warp-uniform addr: 1 sector
        sW[k * 32 + lane] = v;           // conflict-free STS
    }
    __syncthreads();

    float2* __restrict__ out2 = reinterpret_cast<float2*>(out);

    int k = 0;
    int st = 0;
    uint32_t parity = 0;
    for (long long c = bid; c < NCHUNKS; c += NCTAS, k++) {
        mbar_wait(mb[st], parity);

        // 2 elems/thread: one LDS.128, two conflict-free gathers,
        // one direct streaming store (no staging, no store barrier).
        float2 r;
        if (is64) {
            const ulonglong2 v =
                *reinterpret_cast<const ulonglong2*>(&ibuf[st][tid * 2]);
            r.x = sW[((int)v.x - 1) * 32 + lane];
            r.y = sW[((int)v.y - 1) * 32 + lane];
        } else {
            const uint2 v =
                *reinterpret_cast<const uint2*>(
                    reinterpret_cast<const char*>(&ibuf[st][0]) + tid * 8);
            r.x = sW[((int)v.x - 1) * 32 + lane];
            r.y = sW[((int)v.y - 1) * 32 + lane];
        }
        __stcs(out2 + c * (EPC / 2) + tid, r);

        __syncthreads();   // ibuf[st] fully consumed by all threads

        if (tid == 0) {
            long long cn = c + (long long)NSTAGES * NCTAS;
            if (cn < NCHUNKS)
                bulk_load(ib[st], gsrc + cn * ic_bytes, ic_bytes, mb[st]);
        }

        if (++st == NSTAGES) { st = 0; parity ^= 1; }
    }
}

extern "C" void kernel_launch(void* const* d_in, const int* in_sizes, int n_in,
                              void* d_out, int out_size)
{
    const uint32_t* idx = (const uint32_t*)d_in[0];  // inputs [16384, 200]
    const float*    W   = (const float*)d_in[1];     // [200, 1]
    float*          out = (float*)d_out;

    bias_gather_kernel<<<NCTAS, TPB>>>(idx, W, out);
}